// round 6
// baseline (speedup 1.0000x reference)
#include <cuda_runtime.h>
#include <cstdint>

#define Bn    16
#define NCn   80
#define An    33600
#define QAn   (An/4)          /* 8400 quads per frame */
#define PRE   750
#define POST  30
#define CH    256
#define HB2   8192            /* smem hist bins: bits(1-s)>>17 <= 0x1FC0 */
#define CAP   1024

#define OUT_CLS_OFF  0
#define OUT_REG_OFF  (Bn*POST*CH)
#define OUT_BOX_OFF  (2*Bn*POST*CH)
#define OUT_SC_OFF   (2*Bn*POST*CH + Bn*POST*4)

__device__ float              g_maxs[Bn * An];
__device__ int                g_cls[Bn * An];
__device__ unsigned long long g_cand[Bn * CAP];
__device__ int                g_cnt[Bn];
__device__ int                g_thresh[Bn];

static __device__ __forceinline__ unsigned score_bin(float s) {
    return __float_as_uint(1.0f - s) >> 17;   // bin ascending <=> score descending
}

// ---------------------------------------------------------------------------
// K1: pure streaming max+argmax over 80 classes (proven R1 form, ~30us).
// ---------------------------------------------------------------------------
__global__ void k_maxscore(const float* __restrict__ raw) {
    int t = blockIdx.x * blockDim.x + threadIdx.x;
    if (t >= Bn * QAn) return;
    int b = t / QAn;
    int q = t - b * QAn;

    const float* base = raw + (size_t)b * 84 * An + (size_t)4 * An;

    float4 best = __ldg((const float4*)base + q);
    int4 bi = make_int4(0, 0, 0, 0);
#pragma unroll 4
    for (int c = 1; c < NCn; ++c) {
        float4 v = __ldg((const float4*)(base + (size_t)c * An) + q);
        if (v.x > best.x) { best.x = v.x; bi.x = c; }
        if (v.y > best.y) { best.y = v.y; bi.y = c; }
        if (v.z > best.z) { best.z = v.z; bi.z = c; }
        if (v.w > best.w) { best.w = v.w; bi.w = c; }
    }
    ((float4*)g_maxs)[t] = best;
    ((int4*)g_cls)[t] = bi;
}

// ---------------------------------------------------------------------------
// K2: per-frame smem histogram (8192 bins) over max scores + pivot threshold.
// One block per frame. Warp-aggregated smem atomics.
// ---------------------------------------------------------------------------
__global__ __launch_bounds__(1024) void k_pivot() {
    const int b = blockIdx.x;
    const int tid = threadIdx.x;

    __shared__ unsigned hist[HB2];          // 32 KB
    __shared__ unsigned wsum[32];

    for (int i = tid; i < HB2; i += 1024) hist[i] = 0;
    __syncthreads();

    const float4* msv = (const float4*)(g_maxs + (size_t)b * An);
    const int IT = (QAn + 1023) / 1024;     // 9
    for (int it = 0; it < IT; ++it) {
        int q = it * 1024 + tid;
        bool valid = (q < QAn);
        float4 s = valid ? msv[q] : make_float4(0.f, 0.f, 0.f, 0.f);
        unsigned d[4];
        d[0] = valid ? score_bin(s.x) : 0xFFFFFFFFu;
        d[1] = valid ? score_bin(s.y) : 0xFFFFFFFFu;
        d[2] = valid ? score_bin(s.z) : 0xFFFFFFFFu;
        d[3] = valid ? score_bin(s.w) : 0xFFFFFFFFu;
#pragma unroll
        for (int l = 0; l < 4; ++l) {
            unsigned grp = __match_any_sync(0xFFFFFFFFu, d[l]);
            if (d[l] != 0xFFFFFFFFu) {
                if ((int)(tid & 31) == (__ffs(grp) - 1))
                    atomicAdd(&hist[d[l]], (unsigned)__popc(grp));
            }
        }
    }
    __syncthreads();

    // block scan over 8 bins per thread
    const int base = tid * 8;
    unsigned s = 0;
#pragma unroll
    for (int i = 0; i < 2; ++i) {
        uint4 v = ((const uint4*)(hist + base))[i];
        s += v.x + v.y + v.z + v.w;
    }
    unsigned lane = tid & 31, wid = tid >> 5;
    unsigned v = s;
#pragma unroll
    for (int o = 1; o < 32; o <<= 1) {
        unsigned n = __shfl_up_sync(0xFFFFFFFFu, v, o);
        if (lane >= o) v += n;
    }
    if (lane == 31) wsum[wid] = v;
    __syncthreads();
    if (wid == 0) {
        unsigned w = wsum[lane];
#pragma unroll
        for (int o = 1; o < 32; o <<= 1) {
            unsigned n = __shfl_up_sync(0xFFFFFFFFu, w, o);
            if (lane >= o) w += n;
        }
        wsum[lane] = w;
    }
    __syncthreads();
    unsigned incl = v + (wid ? wsum[wid - 1] : 0u);
    unsigned excl = incl - s;

    if (excl < PRE && incl >= PRE) {
        unsigned c = excl;
        int p = base;
        while (c + hist[p] < PRE) { c += hist[p]; ++p; }
        g_thresh[b] = p;
    }
    if (tid == 0) g_cnt[b] = 0;
}

// ---------------------------------------------------------------------------
// K3: chip-wide compaction — true keys of all anchors with bin <= threshold.
// ---------------------------------------------------------------------------
__global__ void k_compact() {
    int t = blockIdx.x * blockDim.x + threadIdx.x;
    if (t >= Bn * QAn) return;
    int b = t / QAn;
    int q = t - b * QAn;

    unsigned th = (unsigned)g_thresh[b];
    float4 s4 = ((const float4*)g_maxs)[t];
    float sv[4] = {s4.x, s4.y, s4.z, s4.w};
#pragma unroll
    for (int l = 0; l < 4; ++l) {
        if (score_bin(sv[l]) <= th) {
            int pos = atomicAdd(&g_cnt[b], 1);
            if (pos < CAP) {
                int a = q * 4 + l;
                g_cand[b * CAP + pos] =
                    ((unsigned long long)__float_as_uint(sv[l]) << 32) | (unsigned)(~a);
            }
        }
    }
}

// ---------------------------------------------------------------------------
// K4: per-frame — sort candidates (exact top-750 order), NMS, fused gather.
// ---------------------------------------------------------------------------
__global__ __launch_bounds__(1024) void k_select(const float* __restrict__ raw,
                                                 const float* __restrict__ vid,
                                                 const float* __restrict__ reg,
                                                 float* __restrict__ out) {
    const int b = blockIdx.x;
    const int tid = threadIdx.x;
    const int T = 1024;

    __shared__ unsigned long long keys[1024];
    __shared__ float bx1[PRE], by1[PRE], bx2[PRE], by2[PRE], barea[PRE];
    __shared__ int bcls[PRE];
    __shared__ int keep[PRE];
    __shared__ unsigned pairs[1024];
    __shared__ int sh_final[POST];
    __shared__ unsigned hist[256];
    __shared__ unsigned long long sh_prefix;
    __shared__ unsigned sh_k;
    __shared__ int sh_pos, sh_maxbits, sh_np, sh_kept, sh_fallback;

    const float* ms = g_maxs + (size_t)b * An;
    const int* cl = g_cls + (size_t)b * An;

    int cnt = g_cnt[b];

    if (cnt <= CAP) {
        keys[tid] = (tid < cnt) ? g_cand[b * CAP + tid] : 0ULL;
    } else {
        // exact fallback (provably ~never): 8-pass 64-bit radix select over ms
        unsigned long long prefix = 0ULL;
        unsigned kk = PRE;
        const int ITER = (An + T - 1) / T;
        for (int pass = 0; pass < 8; ++pass) {
            int shift = 56 - pass * 8;
            unsigned long long hi_mask = (pass == 0) ? 0ULL : (~0ULL << (unsigned)(shift + 8));
            for (int i = tid; i < 256; i += T) hist[i] = 0;
            __syncthreads();
            for (int it = 0; it < ITER; ++it) {
                int a = it * T + tid;
                if (a < An) {
                    unsigned long long key =
                        ((unsigned long long)__float_as_uint(ms[a]) << 32) | (unsigned)(~a);
                    if ((key & hi_mask) == prefix)
                        atomicAdd(&hist[(unsigned)(key >> shift) & 255u], 1u);
                }
            }
            __syncthreads();
            if (tid == 0) {
                unsigned cum = 0; int d = 255;
                for (; d >= 0; --d) {
                    unsigned c = hist[d];
                    if (cum + c >= kk) break;
                    cum += c;
                }
                if (d < 0) d = 0;
                prefix |= ((unsigned long long)d) << shift;
                kk -= cum;
                sh_prefix = prefix; sh_k = kk;
            }
            __syncthreads();
            prefix = sh_prefix; kk = sh_k;
            __syncthreads();
        }
        if (tid == 0) sh_pos = 0;
        __syncthreads();
        for (int a = tid; a < An; a += T) {
            unsigned long long key =
                ((unsigned long long)__float_as_uint(ms[a]) << 32) | (unsigned)(~a);
            if (key >= prefix) {
                int pos = atomicAdd(&sh_pos, 1);
                if (pos < 1024) keys[pos] = key;
            }
        }
        __syncthreads();
        int c2 = sh_pos; if (c2 > 1024) c2 = 1024;
        for (int i = c2 + tid; i < 1024; i += T) keys[i] = 0ULL;
    }
    __syncthreads();

    // ---- hybrid bitonic sort, descending by true key ----
    {
        unsigned long long v = keys[tid];
        for (int k2 = 2; k2 <= 1024; k2 <<= 1) {
            bool dirmax = ((tid & k2) == 0);
            for (int j = k2 >> 1; j >= 1; j >>= 1) {
                unsigned long long o;
                if (j >= 32) {
                    keys[tid] = v;
                    __syncthreads();
                    o = keys[tid ^ j];
                    __syncthreads();
                } else {
                    o = __shfl_xor_sync(0xFFFFFFFFu, v, j);
                }
                bool lower = ((tid & j) == 0);
                bool takeMax = (lower == dirmax);
                bool gt = (v > o);
                v = (takeMax == gt) ? v : o;
            }
        }
        keys[tid] = v;
        __syncthreads();
    }

    // ---- boxes/classes for sorted top-750; max coordinate ----
    if (tid == 0) { sh_maxbits = 0; sh_fallback = 0; }
    __syncthreads();
    if (tid < PRE) {
        int i = tid;
        int a = (int)(~(unsigned)(keys[i] & 0xFFFFFFFFULL));
        const float* rb = raw + (size_t)b * 84 * An;
        float x1 = rb[0 * (size_t)An + a];
        float y1 = rb[1 * (size_t)An + a];
        float x2 = rb[2 * (size_t)An + a];
        float y2 = rb[3 * (size_t)An + a];
        bx1[i] = x1; by1[i] = y1; bx2[i] = x2; by2[i] = y2;
        bcls[i] = cl[a];
        float m = fmaxf(fmaxf(x1, y1), fmaxf(x2, y2));
        atomicMax(&sh_maxbits, __float_as_int(m));
    }
    __syncthreads();

    float off_scale = __int_as_float(sh_maxbits) + 1.0f;
    if (tid < PRE) {
        int i = tid;
        float off = (float)bcls[i] * off_scale;
        float x1 = bx1[i] + off, y1 = by1[i] + off;
        float x2 = bx2[i] + off, y2 = by2[i] + off;
        bx1[i] = x1; by1[i] = y1; bx2[i] = x2; by2[i] = y2;
        barea[i] = (x2 - x1) * (y2 - y1);
    }
    __syncthreads();

    // ---- NMS: windowed conflict pairs + serial resolve ----
    {
        int W = 64;
        for (;;) {
            if (tid == 0) sh_np = 0;
            if (tid < PRE) keep[tid] = 1;
            __syncthreads();

            for (int p = tid; p < W * PRE; p += T) {
                int i = p / PRE;
                int j = p - i * PRE;
                if (j > i && bcls[i] == bcls[j]) {
                    float iw = fmaxf(fminf(bx2[i], bx2[j]) - fmaxf(bx1[i], bx1[j]), 0.0f);
                    float ih = fmaxf(fminf(by2[i], by2[j]) - fmaxf(by1[i], by1[j]), 0.0f);
                    float inter = iw * ih;
                    float iou = __fdiv_rn(inter, barea[i] + barea[j] - inter);
                    if (iou > 0.4f) {
                        int k = atomicAdd(&sh_np, 1);
                        if (k < 1024) pairs[k] = ((unsigned)i << 10) | (unsigned)j;
                    }
                }
            }
            __syncthreads();
            int np = sh_np;
            if (np > 1024) { if (tid == 0) sh_fallback = 1; __syncthreads(); break; }

            if (tid == 0) {
                for (int a2 = 1; a2 < np; ++a2) {
                    unsigned v = pairs[a2];
                    int b2 = a2 - 1;
                    while (b2 >= 0 && pairs[b2] > v) { pairs[b2 + 1] = pairs[b2]; --b2; }
                    pairs[b2 + 1] = v;
                }
                for (int p2 = 0; p2 < np; ++p2) {
                    unsigned v = pairs[p2];
                    int i = (int)(v >> 10), j = (int)(v & 1023u);
                    if (keep[i]) keep[j] = 0;
                }
                int kept = 0;
                for (int i = 0; i < W && kept < POST; ++i) kept += keep[i];
                sh_kept = kept;
            }
            __syncthreads();
            if (sh_kept >= POST || W >= PRE) break;
            W = (W * 4 < PRE) ? W * 4 : PRE;
            __syncthreads();
        }
    }

    if (sh_fallback) {  // pathological conflict counts only
        if (tid < PRE) keep[tid] = 1;
        __syncthreads();
        int i = 0, kept = 0;
        while (i < PRE && kept < POST) {
            while (i < PRE && !keep[i]) ++i;
            if (i >= PRE) break;
            float X1 = bx1[i], Y1 = by1[i], X2 = bx2[i], Y2 = by2[i], AR = barea[i];
            int CI = bcls[i];
            for (int j = i + 1 + tid; j < PRE; j += T) {
                if (keep[j] && bcls[j] == CI) {
                    float iw = fmaxf(fminf(X2, bx2[j]) - fmaxf(X1, bx1[j]), 0.0f);
                    float ih = fmaxf(fminf(Y2, by2[j]) - fmaxf(Y1, by1[j]), 0.0f);
                    float inter = iw * ih;
                    float iou = __fdiv_rn(inter, AR + barea[j] - inter);
                    if (iou > 0.4f) keep[j] = 0;
                }
            }
            ++kept; ++i;
            __syncthreads();
        }
    }

    // ---- stable-partition: first 30 kept, then unkept fill ----
    if (tid == 0) {
        int c2 = 0;
        for (int i = 0; i < PRE && c2 < POST; ++i)
            if (keep[i]) sh_final[c2++] = i;
        for (int i = 0; i < PRE && c2 < POST; ++i)
            if (!keep[i]) sh_final[c2++] = i;
    }
    __syncthreads();

    // ---- fused gather ----
    for (int w2 = tid; w2 < POST * 128; w2 += T) {
        int c = w2 >> 7;
        int f = w2 & 127;
        int i = sh_final[c];
        int a = (int)(~(unsigned)(keys[i] & 0xFFFFFFFFULL));
        size_t r = (size_t)b * POST + c;
        size_t row = ((size_t)b * An + a) * CH;
        if (f < 64)
            ((float4*)(out + OUT_CLS_OFF))[r * 64 + f] = __ldg((const float4*)(vid + row) + f);
        else
            ((float4*)(out + OUT_REG_OFF))[r * 64 + (f - 64)] = __ldg((const float4*)(reg + row) + (f - 64));
    }
    if (tid < POST * 4) {
        int c = tid >> 2, d = tid & 3;
        int i = sh_final[c];
        int a = (int)(~(unsigned)(keys[i] & 0xFFFFFFFFULL));
        out[OUT_BOX_OFF + (b * POST + c) * 4 + d] = raw[(size_t)b * 84 * An + (size_t)d * An + a];
    }
    if (tid >= 128 && tid < 128 + POST) {
        int c = tid - 128;
        int i = sh_final[c];
        out[OUT_SC_OFF + b * POST + c] = __uint_as_float((unsigned)(keys[i] >> 32));
    }
}

// ---------------------------------------------------------------------------
extern "C" void kernel_launch(void* const* d_in, const int* in_sizes, int n_in,
                              void* d_out, int out_size) {
    const float* raw = (const float*)d_in[0];
    const float* vid = (const float*)d_in[1];
    const float* reg = (const float*)d_in[2];
    float* out = (float*)d_out;

    int threads1 = 256;
    int blocks1 = (Bn * QAn + threads1 - 1) / threads1;
    k_maxscore<<<blocks1, threads1>>>(raw);
    k_pivot<<<Bn, 1024>>>();
    k_compact<<<blocks1, threads1>>>();
    k_select<<<Bn, 1024>>>(raw, vid, reg, out);
}

// round 7
// speedup vs baseline: 1.3124x; 1.3124x over previous
#include <cuda_runtime.h>
#include <cstdint>

#define Bn    16
#define NCn   80
#define An    33600
#define QAn   (An/4)          /* 8400 quads per frame */
#define FBLK  33              /* 33*256 = 8448 >= 8400 */
#define PRE   750
#define POST  30
#define CH    256
#define HBN   2048            /* bins: bits(1-s)>>19 <= 0x7F0 */
#define CAP   1024

#define OUT_CLS_OFF  0
#define OUT_REG_OFF  (Bn*POST*CH)
#define OUT_BOX_OFF  (2*Bn*POST*CH)
#define OUT_SC_OFF   (2*Bn*POST*CH + Bn*POST*4)

__device__ float              g_maxs[Bn * An];
__device__ int                g_cls[Bn * An];
__device__ unsigned           g_hist[Bn * HBN];   // zero at load; self-resetting
__device__ unsigned long long g_cand[Bn * CAP];
__device__ int                g_cnt[Bn];
__device__ int                g_thresh[Bn];

static __device__ __forceinline__ unsigned score_bin(float s) {
    return __float_as_uint(1.0f - s) >> 19;   // bin ascending <=> score descending
}

// ---------------------------------------------------------------------------
// K1: pure streaming max+argmax over 80 classes (proven form, ~30us).
// ---------------------------------------------------------------------------
__global__ void k_maxscore(const float* __restrict__ raw) {
    int t = blockIdx.x * blockDim.x + threadIdx.x;
    if (t >= Bn * QAn) return;
    int b = t / QAn;
    int q = t - b * QAn;

    const float* base = raw + (size_t)b * 84 * An + (size_t)4 * An;

    float4 best = __ldg((const float4*)base + q);
    int4 bi = make_int4(0, 0, 0, 0);
#pragma unroll 4
    for (int c = 1; c < NCn; ++c) {
        float4 v = __ldg((const float4*)(base + (size_t)c * An) + q);
        if (v.x > best.x) { best.x = v.x; bi.x = c; }
        if (v.y > best.y) { best.y = v.y; bi.y = c; }
        if (v.z > best.z) { best.z = v.z; bi.z = c; }
        if (v.w > best.w) { best.w = v.w; bi.w = c; }
    }
    ((float4*)g_maxs)[t] = best;
    ((int4*)g_cls)[t] = bi;
}

// ---------------------------------------------------------------------------
// K2: chip-wide histogram build (warp-aggregated global atomics).
// 2D grid so every block (hence warp) serves exactly one frame.
// ---------------------------------------------------------------------------
__global__ __launch_bounds__(256) void k_hist() {
    const int b = blockIdx.y;
    const int q = blockIdx.x * 256 + threadIdx.x;
    const bool valid = (q < QAn);
    unsigned* H = g_hist + (size_t)b * HBN;

    float4 s = valid ? ((const float4*)g_maxs)[b * QAn + q]
                     : make_float4(0.f, 0.f, 0.f, 0.f);
    unsigned d[4];
    d[0] = valid ? score_bin(s.x) : 0xFFFFFFFFu;
    d[1] = valid ? score_bin(s.y) : 0xFFFFFFFFu;
    d[2] = valid ? score_bin(s.z) : 0xFFFFFFFFu;
    d[3] = valid ? score_bin(s.w) : 0xFFFFFFFFu;
#pragma unroll
    for (int l = 0; l < 4; ++l) {
        unsigned grp = __match_any_sync(0xFFFFFFFFu, d[l]);
        if (d[l] != 0xFFFFFFFFu) {
            if ((int)(threadIdx.x & 31) == (__ffs(grp) - 1))
                atomicAdd(&H[d[l]], (unsigned)__popc(grp));
        }
    }
}

// ---------------------------------------------------------------------------
// K3: per-frame pivot from the 2048-bin histogram; zero hist; reset counter.
// 16 blocks x 256 threads; only touches 8 KB per frame.
// ---------------------------------------------------------------------------
__global__ __launch_bounds__(256) void k_pivot() {
    const int b = blockIdx.x;
    const int tid = threadIdx.x;
    unsigned* H = g_hist + (size_t)b * HBN;

    __shared__ unsigned wsum[8];

    const int base = tid * 8;
    uint4 v0 = ((const uint4*)(H + base))[0];
    uint4 v1 = ((const uint4*)(H + base))[1];
    unsigned s = v0.x + v0.y + v0.z + v0.w + v1.x + v1.y + v1.z + v1.w;

    unsigned lane = tid & 31, wid = tid >> 5;
    unsigned v = s;
#pragma unroll
    for (int o = 1; o < 32; o <<= 1) {
        unsigned n = __shfl_up_sync(0xFFFFFFFFu, v, o);
        if (lane >= o) v += n;
    }
    if (lane == 31) wsum[wid] = v;
    __syncthreads();
    if (tid < 8) {
        unsigned w = wsum[tid];
#pragma unroll
        for (int o = 1; o < 8; o <<= 1) {
            unsigned n = __shfl_up_sync(0xFFu, w, o);
            if ((int)tid >= o) w += n;
        }
        wsum[tid] = w;
    }
    __syncthreads();
    unsigned incl = v + (wid ? wsum[wid - 1] : 0u);
    unsigned excl = incl - s;

    if (excl < PRE && incl >= PRE) {
        unsigned bins[8] = {v0.x, v0.y, v0.z, v0.w, v1.x, v1.y, v1.z, v1.w};
        unsigned c = excl;
        int p = 0;
        while (c + bins[p] < PRE) { c += bins[p]; ++p; }
        g_thresh[b] = base + p;
    }
    __syncthreads();
    ((uint4*)(H + base))[0] = make_uint4(0, 0, 0, 0);
    ((uint4*)(H + base))[1] = make_uint4(0, 0, 0, 0);
    if (tid == 0) g_cnt[b] = 0;
}

// ---------------------------------------------------------------------------
// K4: chip-wide compaction, warp-aggregated counter atomics.
// ---------------------------------------------------------------------------
__global__ __launch_bounds__(256) void k_compact() {
    const int b = blockIdx.y;
    const int q = blockIdx.x * 256 + threadIdx.x;
    const bool valid = (q < QAn);
    const unsigned th = (unsigned)g_thresh[b];

    float4 s4 = valid ? ((const float4*)g_maxs)[b * QAn + q]
                      : make_float4(-1.f, -1.f, -1.f, -1.f);   // bin(2.0) > th
    float sv[4] = {s4.x, s4.y, s4.z, s4.w};
#pragma unroll
    for (int l = 0; l < 4; ++l) {
        bool take = (score_bin(sv[l]) <= th);
        unsigned bal = __ballot_sync(0xFFFFFFFFu, take);
        if (take) {
            int lane = (int)(threadIdx.x & 31);
            int leader = __ffs(bal) - 1;
            int basep;
            if (lane == leader) basep = atomicAdd(&g_cnt[b], __popc(bal));
            basep = __shfl_sync(bal, basep, leader);
            int pos = basep + __popc(bal & ((1u << lane) - 1u));
            if (pos < CAP) {
                int a = q * 4 + l;
                g_cand[b * CAP + pos] =
                    ((unsigned long long)__float_as_uint(sv[l]) << 32) | (unsigned)(~a);
            }
        }
    }
}

// ---------------------------------------------------------------------------
// K5: per-frame — sort candidates (exact top-750 order), NMS, fused gather.
// ---------------------------------------------------------------------------
__global__ __launch_bounds__(1024) void k_select(const float* __restrict__ raw,
                                                 const float* __restrict__ vid,
                                                 const float* __restrict__ reg,
                                                 float* __restrict__ out) {
    const int b = blockIdx.x;
    const int tid = threadIdx.x;
    const int T = 1024;

    __shared__ unsigned long long keys[1024];
    __shared__ float bx1[PRE], by1[PRE], bx2[PRE], by2[PRE], barea[PRE];
    __shared__ int bcls[PRE];
    __shared__ int keep[PRE];
    __shared__ unsigned pairs[1024];
    __shared__ int sh_final[POST];
    __shared__ unsigned hist[256];
    __shared__ unsigned long long sh_prefix;
    __shared__ unsigned sh_k;
    __shared__ int sh_pos, sh_maxbits, sh_np, sh_kept, sh_fallback;

    const float* ms = g_maxs + (size_t)b * An;
    const int* cl = g_cls + (size_t)b * An;

    int cnt = g_cnt[b];

    if (cnt <= CAP) {
        keys[tid] = (tid < cnt) ? g_cand[b * CAP + tid] : 0ULL;
    } else {
        // exact fallback (provably ~never): 8-pass 64-bit radix select over ms
        unsigned long long prefix = 0ULL;
        unsigned kk = PRE;
        const int ITER = (An + T - 1) / T;
        for (int pass = 0; pass < 8; ++pass) {
            int shift = 56 - pass * 8;
            unsigned long long hi_mask = (pass == 0) ? 0ULL : (~0ULL << (unsigned)(shift + 8));
            for (int i = tid; i < 256; i += T) hist[i] = 0;
            __syncthreads();
            for (int it = 0; it < ITER; ++it) {
                int a = it * T + tid;
                if (a < An) {
                    unsigned long long key =
                        ((unsigned long long)__float_as_uint(ms[a]) << 32) | (unsigned)(~a);
                    if ((key & hi_mask) == prefix)
                        atomicAdd(&hist[(unsigned)(key >> shift) & 255u], 1u);
                }
            }
            __syncthreads();
            if (tid == 0) {
                unsigned cum = 0; int d = 255;
                for (; d >= 0; --d) {
                    unsigned c = hist[d];
                    if (cum + c >= kk) break;
                    cum += c;
                }
                if (d < 0) d = 0;
                prefix |= ((unsigned long long)d) << shift;
                kk -= cum;
                sh_prefix = prefix; sh_k = kk;
            }
            __syncthreads();
            prefix = sh_prefix; kk = sh_k;
            __syncthreads();
        }
        if (tid == 0) sh_pos = 0;
        __syncthreads();
        for (int a = tid; a < An; a += T) {
            unsigned long long key =
                ((unsigned long long)__float_as_uint(ms[a]) << 32) | (unsigned)(~a);
            if (key >= prefix) {
                int pos = atomicAdd(&sh_pos, 1);
                if (pos < 1024) keys[pos] = key;
            }
        }
        __syncthreads();
        int c2 = sh_pos; if (c2 > 1024) c2 = 1024;
        for (int i = c2 + tid; i < 1024; i += T) keys[i] = 0ULL;
    }
    __syncthreads();

    // ---- hybrid bitonic sort, descending by true key ----
    {
        unsigned long long v = keys[tid];
        for (int k2 = 2; k2 <= 1024; k2 <<= 1) {
            bool dirmax = ((tid & k2) == 0);
            for (int j = k2 >> 1; j >= 1; j >>= 1) {
                unsigned long long o;
                if (j >= 32) {
                    keys[tid] = v;
                    __syncthreads();
                    o = keys[tid ^ j];
                    __syncthreads();
                } else {
                    o = __shfl_xor_sync(0xFFFFFFFFu, v, j);
                }
                bool lower = ((tid & j) == 0);
                bool takeMax = (lower == dirmax);
                bool gt = (v > o);
                v = (takeMax == gt) ? v : o;
            }
        }
        keys[tid] = v;
        __syncthreads();
    }

    // ---- boxes/classes for sorted top-750; max coordinate ----
    if (tid == 0) { sh_maxbits = 0; sh_fallback = 0; }
    __syncthreads();
    if (tid < PRE) {
        int i = tid;
        int a = (int)(~(unsigned)(keys[i] & 0xFFFFFFFFULL));
        const float* rb = raw + (size_t)b * 84 * An;
        float x1 = rb[0 * (size_t)An + a];
        float y1 = rb[1 * (size_t)An + a];
        float x2 = rb[2 * (size_t)An + a];
        float y2 = rb[3 * (size_t)An + a];
        bx1[i] = x1; by1[i] = y1; bx2[i] = x2; by2[i] = y2;
        bcls[i] = cl[a];
        float m = fmaxf(fmaxf(x1, y1), fmaxf(x2, y2));
        atomicMax(&sh_maxbits, __float_as_int(m));
    }
    __syncthreads();

    float off_scale = __int_as_float(sh_maxbits) + 1.0f;
    if (tid < PRE) {
        int i = tid;
        float off = (float)bcls[i] * off_scale;
        float x1 = bx1[i] + off, y1 = by1[i] + off;
        float x2 = bx2[i] + off, y2 = by2[i] + off;
        bx1[i] = x1; by1[i] = y1; bx2[i] = x2; by2[i] = y2;
        barea[i] = (x2 - x1) * (y2 - y1);
    }
    __syncthreads();

    // ---- NMS: windowed conflict pairs + serial resolve ----
    {
        int W = 64;
        for (;;) {
            if (tid == 0) sh_np = 0;
            if (tid < PRE) keep[tid] = 1;
            __syncthreads();

            for (int p = tid; p < W * PRE; p += T) {
                int i = p / PRE;
                int j = p - i * PRE;
                if (j > i && bcls[i] == bcls[j]) {
                    float iw = fmaxf(fminf(bx2[i], bx2[j]) - fmaxf(bx1[i], bx1[j]), 0.0f);
                    float ih = fmaxf(fminf(by2[i], by2[j]) - fmaxf(by1[i], by1[j]), 0.0f);
                    float inter = iw * ih;
                    float iou = __fdiv_rn(inter, barea[i] + barea[j] - inter);
                    if (iou > 0.4f) {
                        int k = atomicAdd(&sh_np, 1);
                        if (k < 1024) pairs[k] = ((unsigned)i << 10) | (unsigned)j;
                    }
                }
            }
            __syncthreads();
            int np = sh_np;
            if (np > 1024) { if (tid == 0) sh_fallback = 1; __syncthreads(); break; }

            if (tid == 0) {
                for (int a2 = 1; a2 < np; ++a2) {
                    unsigned v = pairs[a2];
                    int b2 = a2 - 1;
                    while (b2 >= 0 && pairs[b2] > v) { pairs[b2 + 1] = pairs[b2]; --b2; }
                    pairs[b2 + 1] = v;
                }
                for (int p2 = 0; p2 < np; ++p2) {
                    unsigned v = pairs[p2];
                    int i = (int)(v >> 10), j = (int)(v & 1023u);
                    if (keep[i]) keep[j] = 0;
                }
                int kept = 0;
                for (int i = 0; i < W && kept < POST; ++i) kept += keep[i];
                sh_kept = kept;
            }
            __syncthreads();
            if (sh_kept >= POST || W >= PRE) break;
            W = (W * 4 < PRE) ? W * 4 : PRE;
            __syncthreads();
        }
    }

    if (sh_fallback) {  // pathological conflict counts only
        if (tid < PRE) keep[tid] = 1;
        __syncthreads();
        int i = 0, kept = 0;
        while (i < PRE && kept < POST) {
            while (i < PRE && !keep[i]) ++i;
            if (i >= PRE) break;
            float X1 = bx1[i], Y1 = by1[i], X2 = bx2[i], Y2 = by2[i], AR = barea[i];
            int CI = bcls[i];
            for (int j = i + 1 + tid; j < PRE; j += T) {
                if (keep[j] && bcls[j] == CI) {
                    float iw = fmaxf(fminf(X2, bx2[j]) - fmaxf(X1, bx1[j]), 0.0f);
                    float ih = fmaxf(fminf(Y2, by2[j]) - fmaxf(Y1, by1[j]), 0.0f);
                    float inter = iw * ih;
                    float iou = __fdiv_rn(inter, AR + barea[j] - inter);
                    if (iou > 0.4f) keep[j] = 0;
                }
            }
            ++kept; ++i;
            __syncthreads();
        }
    }

    // ---- stable-partition: first 30 kept, then unkept fill ----
    if (tid == 0) {
        int c2 = 0;
        for (int i = 0; i < PRE && c2 < POST; ++i)
            if (keep[i]) sh_final[c2++] = i;
        for (int i = 0; i < PRE && c2 < POST; ++i)
            if (!keep[i]) sh_final[c2++] = i;
    }
    __syncthreads();

    // ---- fused gather ----
    for (int w2 = tid; w2 < POST * 128; w2 += T) {
        int c = w2 >> 7;
        int f = w2 & 127;
        int i = sh_final[c];
        int a = (int)(~(unsigned)(keys[i] & 0xFFFFFFFFULL));
        size_t r = (size_t)b * POST + c;
        size_t row = ((size_t)b * An + a) * CH;
        if (f < 64)
            ((float4*)(out + OUT_CLS_OFF))[r * 64 + f] = __ldg((const float4*)(vid + row) + f);
        else
            ((float4*)(out + OUT_REG_OFF))[r * 64 + (f - 64)] = __ldg((const float4*)(reg + row) + (f - 64));
    }
    if (tid < POST * 4) {
        int c = tid >> 2, d = tid & 3;
        int i = sh_final[c];
        int a = (int)(~(unsigned)(keys[i] & 0xFFFFFFFFULL));
        out[OUT_BOX_OFF + (b * POST + c) * 4 + d] = raw[(size_t)b * 84 * An + (size_t)d * An + a];
    }
    if (tid >= 128 && tid < 128 + POST) {
        int c = tid - 128;
        int i = sh_final[c];
        out[OUT_SC_OFF + b * POST + c] = __uint_as_float((unsigned)(keys[i] >> 32));
    }
}

// ---------------------------------------------------------------------------
extern "C" void kernel_launch(void* const* d_in, const int* in_sizes, int n_in,
                              void* d_out, int out_size) {
    const float* raw = (const float*)d_in[0];
    const float* vid = (const float*)d_in[1];
    const float* reg = (const float*)d_in[2];
    float* out = (float*)d_out;

    int threads1 = 256;
    int blocks1 = (Bn * QAn + threads1 - 1) / threads1;
    dim3 g2(FBLK, Bn);
    k_maxscore<<<blocks1, threads1>>>(raw);
    k_hist<<<g2, 256>>>();
    k_pivot<<<Bn, 256>>>();
    k_compact<<<g2, 256>>>();
    k_select<<<Bn, 1024>>>(raw, vid, reg, out);
}

// round 8
// speedup vs baseline: 1.3251x; 1.0096x over previous
#include <cuda_runtime.h>
#include <cstdint>

#define Bn    16
#define NCn   80
#define An    33600
#define QAn   (An/4)          /* 8400 quads per frame */
#define FBLK  33              /* 33*256 = 8448 >= 8400 */
#define PRE   750
#define POST  30
#define CH    256
#define NBIN  2048            /* bins: bits(1-s)>>19 <= 0x7F0 */
#define BCAP  64              /* slots per bucket */

#define OUT_CLS_OFF  0
#define OUT_REG_OFF  (Bn*POST*CH)
#define OUT_BOX_OFF  (2*Bn*POST*CH)
#define OUT_SC_OFF   (2*Bn*POST*CH + Bn*POST*4)

__device__ float              g_maxs[Bn * An];
__device__ int                g_cls[Bn * An];
__device__ unsigned           g_bcnt[Bn * NBIN];              // zero at load; select resets
__device__ unsigned long long g_bucket[(size_t)Bn * NBIN * BCAP];

static __device__ __forceinline__ unsigned score_bin(float s) {
    unsigned v = __float_as_uint(1.0f - s) >> 19;  // ascending bin <=> descending score
    return v < (NBIN - 1) ? v : (NBIN - 1);
}

// ---------------------------------------------------------------------------
// K1: pure streaming max+argmax over 80 classes (proven form, ~30us).
// ---------------------------------------------------------------------------
__global__ void k_maxscore(const float* __restrict__ raw) {
    int t = blockIdx.x * blockDim.x + threadIdx.x;
    if (t >= Bn * QAn) return;
    int b = t / QAn;
    int q = t - b * QAn;

    const float* base = raw + (size_t)b * 84 * An + (size_t)4 * An;

    float4 best = __ldg((const float4*)base + q);
    int4 bi = make_int4(0, 0, 0, 0);
#pragma unroll 4
    for (int c = 1; c < NCn; ++c) {
        float4 v = __ldg((const float4*)(base + (size_t)c * An) + q);
        if (v.x > best.x) { best.x = v.x; bi.x = c; }
        if (v.y > best.y) { best.y = v.y; bi.y = c; }
        if (v.z > best.z) { best.z = v.z; bi.z = c; }
        if (v.w > best.w) { best.w = v.w; bi.w = c; }
    }
    ((float4*)g_maxs)[t] = best;
    ((int4*)g_cls)[t] = bi;
}

// ---------------------------------------------------------------------------
// K2: chip-wide bucket scatter. Every anchor's true key goes to its frame's
// score bin; warp-aggregated atomics give contiguous slot ranges.
// ---------------------------------------------------------------------------
__global__ __launch_bounds__(256) void k_scatter() {
    const int b = blockIdx.y;
    const int q = blockIdx.x * 256 + threadIdx.x;
    const bool valid = (q < QAn);
    const int lane = (int)(threadIdx.x & 31);

    float4 s4 = valid ? ((const float4*)g_maxs)[b * QAn + q]
                      : make_float4(0.f, 0.f, 0.f, 0.f);
    float sv[4] = {s4.x, s4.y, s4.z, s4.w};
#pragma unroll
    for (int l = 0; l < 4; ++l) {
        unsigned d = valid ? score_bin(sv[l]) : 0xFFFFFFFFu;
        unsigned grp = __match_any_sync(0xFFFFFFFFu, d);
        if (d != 0xFFFFFFFFu) {
            int leader = __ffs(grp) - 1;
            unsigned rank = __popc(grp & ((1u << lane) - 1u));
            unsigned base;
            if (lane == leader)
                base = atomicAdd(&g_bcnt[b * NBIN + d], (unsigned)__popc(grp));
            base = __shfl_sync(grp, base, leader);
            unsigned slot = base + rank;
            if (slot < BCAP) {
                int a = q * 4 + l;
                g_bucket[((size_t)b * NBIN + d) * BCAP + slot] =
                    ((unsigned long long)__float_as_uint(sv[l]) << 32) | (unsigned)(~a);
            }
        }
    }
}

// ---------------------------------------------------------------------------
// K3: per-frame — pivot from bucket counts, gather superset, sort (exact
// top-750 order), NMS, fused gather. Resets bucket counts for graph replay.
// ---------------------------------------------------------------------------
__global__ __launch_bounds__(1024) void k_select(const float* __restrict__ raw,
                                                 const float* __restrict__ vid,
                                                 const float* __restrict__ reg,
                                                 float* __restrict__ out) {
    const int b = blockIdx.x;
    const int tid = threadIdx.x;
    const int T = 1024;

    __shared__ unsigned long long keys[1024];
    __shared__ unsigned cnts[NBIN];
    __shared__ unsigned prefs[NBIN];
    __shared__ float bx1[PRE], by1[PRE], bx2[PRE], by2[PRE], barea[PRE];
    __shared__ int bcls[PRE];
    __shared__ int keep[PRE];
    __shared__ unsigned pairs[1024];
    __shared__ int sh_final[POST];
    __shared__ unsigned hist[256];
    __shared__ unsigned wsum[32];
    __shared__ unsigned long long sh_prefix;
    __shared__ unsigned sh_k;
    __shared__ int sh_pos, sh_maxbits, sh_np, sh_kept, sh_fallback;
    __shared__ int sh_p, sh_total, sh_over;

    const float* ms = g_maxs + (size_t)b * An;
    const int* cl = g_cls + (size_t)b * An;
    unsigned* BC = g_bcnt + (size_t)b * NBIN;

    // ---- load counts (2 bins/thread), block scan, pivot bin ----
    uint2 c2 = ((const uint2*)BC)[tid];
    cnts[2 * tid] = c2.x;
    cnts[2 * tid + 1] = c2.y;
    unsigned s = c2.x + c2.y;

    unsigned lane = tid & 31, wid = tid >> 5;
    unsigned v = s;
#pragma unroll
    for (int o = 1; o < 32; o <<= 1) {
        unsigned n = __shfl_up_sync(0xFFFFFFFFu, v, o);
        if (lane >= o) v += n;
    }
    if (lane == 31) wsum[wid] = v;
    __syncthreads();
    if (wid == 0) {
        unsigned w = wsum[lane];
#pragma unroll
        for (int o = 1; o < 32; o <<= 1) {
            unsigned n = __shfl_up_sync(0xFFFFFFFFu, w, o);
            if (lane >= o) w += n;
        }
        wsum[lane] = w;
    }
    if (tid == 0) sh_over = 0;
    __syncthreads();
    unsigned incl = v + (wid ? wsum[wid - 1] : 0u);
    unsigned excl = incl - s;
    prefs[2 * tid] = excl;
    prefs[2 * tid + 1] = excl + c2.x;

    if (excl < PRE && incl >= PRE) {
        int p = (excl + c2.x >= PRE) ? (2 * tid) : (2 * tid + 1);
        sh_p = p;
        sh_total = (int)(prefs[p] + cnts[p]);
    }
    __syncthreads();
    int p = sh_p;
    int total = sh_total;
    // overflow check for bins in superset
    if ((int)(2 * tid) <= p && c2.x > BCAP) sh_over = 1;
    if ((int)(2 * tid + 1) <= p && c2.y > BCAP) sh_over = 1;
    __syncthreads();

    if (total <= 1024 && !sh_over) {
        // ---- gather superset from buckets at prefix positions ----
        if (tid >= (unsigned)((total + 0)) ) {} // no-op; padding below
        for (int pass = 0; pass < 2; ++pass) {
            int bin = 2 * tid + pass;
            if (bin <= p) {
                unsigned c = cnts[bin];
                unsigned pf = prefs[bin];
                const unsigned long long* src =
                    g_bucket + ((size_t)b * NBIN + bin) * BCAP;
                for (unsigned k = 0; k < c; ++k) keys[pf + k] = src[k];
            }
        }
        __syncthreads();
        for (int i = total + tid; i < 1024; i += T) keys[i] = 0ULL;
    } else {
        // ---- exact fallback: 8-pass 64-bit radix select over g_maxs ----
        unsigned long long prefix = 0ULL;
        unsigned kk = PRE;
        const int ITER = (An + T - 1) / T;
        for (int pass = 0; pass < 8; ++pass) {
            int shift = 56 - pass * 8;
            unsigned long long hi_mask = (pass == 0) ? 0ULL : (~0ULL << (unsigned)(shift + 8));
            for (int i = tid; i < 256; i += T) hist[i] = 0;
            __syncthreads();
            for (int it = 0; it < ITER; ++it) {
                int a = it * T + tid;
                if (a < An) {
                    unsigned long long key =
                        ((unsigned long long)__float_as_uint(ms[a]) << 32) | (unsigned)(~a);
                    if ((key & hi_mask) == prefix)
                        atomicAdd(&hist[(unsigned)(key >> shift) & 255u], 1u);
                }
            }
            __syncthreads();
            if (tid == 0) {
                unsigned cum = 0; int d = 255;
                for (; d >= 0; --d) {
                    unsigned c = hist[d];
                    if (cum + c >= kk) break;
                    cum += c;
                }
                if (d < 0) d = 0;
                prefix |= ((unsigned long long)d) << shift;
                kk -= cum;
                sh_prefix = prefix; sh_k = kk;
            }
            __syncthreads();
            prefix = sh_prefix; kk = sh_k;
            __syncthreads();
        }
        if (tid == 0) sh_pos = 0;
        __syncthreads();
        for (int a = tid; a < An; a += T) {
            unsigned long long key =
                ((unsigned long long)__float_as_uint(ms[a]) << 32) | (unsigned)(~a);
            if (key >= prefix) {
                int pos = atomicAdd(&sh_pos, 1);
                if (pos < 1024) keys[pos] = key;
            }
        }
        __syncthreads();
        int cpos = sh_pos; if (cpos > 1024) cpos = 1024;
        for (int i = cpos + tid; i < 1024; i += T) keys[i] = 0ULL;
    }

    // reset bucket counts for graph replay (after all reads of BC)
    ((uint2*)BC)[tid] = make_uint2(0, 0);
    __syncthreads();

    // ---- hybrid bitonic sort, descending by true key ----
    {
        unsigned long long vv = keys[tid];
        for (int k2 = 2; k2 <= 1024; k2 <<= 1) {
            bool dirmax = ((tid & k2) == 0);
            for (int j = k2 >> 1; j >= 1; j >>= 1) {
                unsigned long long o;
                if (j >= 32) {
                    keys[tid] = vv;
                    __syncthreads();
                    o = keys[tid ^ j];
                    __syncthreads();
                } else {
                    o = __shfl_xor_sync(0xFFFFFFFFu, vv, j);
                }
                bool lower = ((tid & j) == 0);
                bool takeMax = (lower == dirmax);
                bool gt = (vv > o);
                vv = (takeMax == gt) ? vv : o;
            }
        }
        keys[tid] = vv;
        __syncthreads();
    }

    // ---- boxes/classes for sorted top-750; max coordinate ----
    if (tid == 0) { sh_maxbits = 0; sh_fallback = 0; }
    __syncthreads();
    if (tid < PRE) {
        int i = tid;
        int a = (int)(~(unsigned)(keys[i] & 0xFFFFFFFFULL));
        const float* rb = raw + (size_t)b * 84 * An;
        float x1 = rb[0 * (size_t)An + a];
        float y1 = rb[1 * (size_t)An + a];
        float x2 = rb[2 * (size_t)An + a];
        float y2 = rb[3 * (size_t)An + a];
        bx1[i] = x1; by1[i] = y1; bx2[i] = x2; by2[i] = y2;
        bcls[i] = cl[a];
        float m = fmaxf(fmaxf(x1, y1), fmaxf(x2, y2));
        atomicMax(&sh_maxbits, __float_as_int(m));
    }
    __syncthreads();

    float off_scale = __int_as_float(sh_maxbits) + 1.0f;
    if (tid < PRE) {
        int i = tid;
        float off = (float)bcls[i] * off_scale;
        float x1 = bx1[i] + off, y1 = by1[i] + off;
        float x2 = bx2[i] + off, y2 = by2[i] + off;
        bx1[i] = x1; by1[i] = y1; bx2[i] = x2; by2[i] = y2;
        barea[i] = (x2 - x1) * (y2 - y1);
    }
    __syncthreads();

    // ---- NMS: windowed conflict pairs + serial resolve ----
    {
        int W = 64;
        for (;;) {
            if (tid == 0) sh_np = 0;
            if (tid < PRE) keep[tid] = 1;
            __syncthreads();

            for (int pp = tid; pp < W * PRE; pp += T) {
                int i = pp / PRE;
                int j = pp - i * PRE;
                if (j > i && bcls[i] == bcls[j]) {
                    float iw = fmaxf(fminf(bx2[i], bx2[j]) - fmaxf(bx1[i], bx1[j]), 0.0f);
                    float ih = fmaxf(fminf(by2[i], by2[j]) - fmaxf(by1[i], by1[j]), 0.0f);
                    float inter = iw * ih;
                    float iou = __fdiv_rn(inter, barea[i] + barea[j] - inter);
                    if (iou > 0.4f) {
                        int k = atomicAdd(&sh_np, 1);
                        if (k < 1024) pairs[k] = ((unsigned)i << 10) | (unsigned)j;
                    }
                }
            }
            __syncthreads();
            int np = sh_np;
            if (np > 1024) { if (tid == 0) sh_fallback = 1; __syncthreads(); break; }

            if (tid == 0) {
                for (int a2 = 1; a2 < np; ++a2) {
                    unsigned pv = pairs[a2];
                    int b2 = a2 - 1;
                    while (b2 >= 0 && pairs[b2] > pv) { pairs[b2 + 1] = pairs[b2]; --b2; }
                    pairs[b2 + 1] = pv;
                }
                for (int p2 = 0; p2 < np; ++p2) {
                    unsigned pv = pairs[p2];
                    int i = (int)(pv >> 10), j = (int)(pv & 1023u);
                    if (keep[i]) keep[j] = 0;
                }
                int kept = 0;
                for (int i = 0; i < W && kept < POST; ++i) kept += keep[i];
                sh_kept = kept;
            }
            __syncthreads();
            if (sh_kept >= POST || W >= PRE) break;
            W = (W * 4 < PRE) ? W * 4 : PRE;
            __syncthreads();
        }
    }

    if (sh_fallback) {  // pathological conflict counts only
        if (tid < PRE) keep[tid] = 1;
        __syncthreads();
        int i = 0, kept = 0;
        while (i < PRE && kept < POST) {
            while (i < PRE && !keep[i]) ++i;
            if (i >= PRE) break;
            float X1 = bx1[i], Y1 = by1[i], X2 = bx2[i], Y2 = by2[i], AR = barea[i];
            int CI = bcls[i];
            for (int j = i + 1 + tid; j < PRE; j += T) {
                if (keep[j] && bcls[j] == CI) {
                    float iw = fmaxf(fminf(X2, bx2[j]) - fmaxf(X1, bx1[j]), 0.0f);
                    float ih = fmaxf(fminf(Y2, by2[j]) - fmaxf(Y1, by1[j]), 0.0f);
                    float inter = iw * ih;
                    float iou = __fdiv_rn(inter, AR + barea[j] - inter);
                    if (iou > 0.4f) keep[j] = 0;
                }
            }
            ++kept; ++i;
            __syncthreads();
        }
    }

    // ---- stable-partition: first 30 kept, then unkept fill ----
    if (tid == 0) {
        int c3 = 0;
        for (int i = 0; i < PRE && c3 < POST; ++i)
            if (keep[i]) sh_final[c3++] = i;
        for (int i = 0; i < PRE && c3 < POST; ++i)
            if (!keep[i]) sh_final[c3++] = i;
    }
    __syncthreads();

    // ---- fused gather ----
    for (int w2 = tid; w2 < POST * 128; w2 += T) {
        int c = w2 >> 7;
        int f = w2 & 127;
        int i = sh_final[c];
        int a = (int)(~(unsigned)(keys[i] & 0xFFFFFFFFULL));
        size_t r = (size_t)b * POST + c;
        size_t row = ((size_t)b * An + a) * CH;
        if (f < 64)
            ((float4*)(out + OUT_CLS_OFF))[r * 64 + f] = __ldg((const float4*)(vid + row) + f);
        else
            ((float4*)(out + OUT_REG_OFF))[r * 64 + (f - 64)] = __ldg((const float4*)(reg + row) + (f - 64));
    }
    if (tid < POST * 4) {
        int c = tid >> 2, d = tid & 3;
        int i = sh_final[c];
        int a = (int)(~(unsigned)(keys[i] & 0xFFFFFFFFULL));
        out[OUT_BOX_OFF + (b * POST + c) * 4 + d] = raw[(size_t)b * 84 * An + (size_t)d * An + a];
    }
    if (tid >= 128 && tid < 128 + POST) {
        int c = tid - 128;
        int i = sh_final[c];
        out[OUT_SC_OFF + b * POST + c] = __uint_as_float((unsigned)(keys[i] >> 32));
    }
}

// ---------------------------------------------------------------------------
extern "C" void kernel_launch(void* const* d_in, const int* in_sizes, int n_in,
                              void* d_out, int out_size) {
    const float* raw = (const float*)d_in[0];
    const float* vid = (const float*)d_in[1];
    const float* reg = (const float*)d_in[2];
    float* out = (float*)d_out;

    int threads1 = 256;
    int blocks1 = (Bn * QAn + threads1 - 1) / threads1;
    dim3 g2(FBLK, Bn);
    k_maxscore<<<blocks1, threads1>>>(raw);
    k_scatter<<<g2, 256>>>();
    k_select<<<Bn, 1024>>>(raw, vid, reg, out);
}

// round 9
// speedup vs baseline: 1.4411x; 1.0876x over previous
#include <cuda_runtime.h>
#include <cstdint>

#define Bn    16
#define NCn   80
#define An    33600
#define HAn   (An/2)          /* 16800 half-pairs per frame (K1) */
#define QAn   (An/4)          /* 8400 quads per frame (scatter) */
#define FBLK  33              /* 33*256 = 8448 >= 8400 */
#define PRE   750
#define POST  30
#define CH    256
#define NBIN  2048            /* bins: bits(1-s)>>19, clamped */
#define BCAP  128             /* slots per bucket */

#define OUT_CLS_OFF  0
#define OUT_REG_OFF  (Bn*POST*CH)
#define OUT_BOX_OFF  (2*Bn*POST*CH)
#define OUT_SC_OFF   (2*Bn*POST*CH + Bn*POST*4)

__device__ float              g_maxs[Bn * An];
__device__ int                g_cls[Bn * An];
__device__ unsigned           g_bcnt[Bn * NBIN];              // zero at load; select resets
__device__ unsigned long long g_bucket[(size_t)Bn * NBIN * BCAP];

static __device__ __forceinline__ unsigned score_bin(float s) {
    unsigned v = __float_as_uint(1.0f - s) >> 19;  // ascending bin <=> descending score
    return v < (NBIN - 1) ? v : (NBIN - 1);
}

// ---------------------------------------------------------------------------
// K1: pure streaming max+argmax over 80 classes. float2 per thread:
// same fully-coalesced pattern as the proven float4 kernel, 2x the blocks
// (1050) to lift grid-limited occupancy (41% -> ~82%) and total MLP.
// ---------------------------------------------------------------------------
__global__ void k_maxscore(const float* __restrict__ raw) {
    int t = blockIdx.x * blockDim.x + threadIdx.x;
    if (t >= Bn * HAn) return;
    int b = t / HAn;
    int h = t - b * HAn;

    const float* base = raw + (size_t)b * 84 * An + (size_t)4 * An;

    float2 best = __ldg((const float2*)base + h);
    int2 bi = make_int2(0, 0);
#pragma unroll 4
    for (int c = 1; c < NCn; ++c) {
        float2 v = __ldg((const float2*)(base + (size_t)c * An) + h);
        if (v.x > best.x) { best.x = v.x; bi.x = c; }
        if (v.y > best.y) { best.y = v.y; bi.y = c; }
    }
    ((float2*)g_maxs)[t] = best;
    ((int2*)g_cls)[t] = bi;
}

// ---------------------------------------------------------------------------
// K2: chip-wide bucket scatter. Warp-aggregated slot atomics.
// ---------------------------------------------------------------------------
__global__ __launch_bounds__(256) void k_scatter() {
    const int b = blockIdx.y;
    const int q = blockIdx.x * 256 + threadIdx.x;
    const bool valid = (q < QAn);
    const int lane = (int)(threadIdx.x & 31);

    float4 s4 = valid ? ((const float4*)g_maxs)[b * QAn + q]
                      : make_float4(0.f, 0.f, 0.f, 0.f);
    float sv[4] = {s4.x, s4.y, s4.z, s4.w};
#pragma unroll
    for (int l = 0; l < 4; ++l) {
        unsigned d = valid ? score_bin(sv[l]) : 0xFFFFFFFFu;
        unsigned grp = __match_any_sync(0xFFFFFFFFu, d);
        if (d != 0xFFFFFFFFu) {
            int leader = __ffs(grp) - 1;
            unsigned rank = __popc(grp & ((1u << lane) - 1u));
            unsigned base;
            if (lane == leader)
                base = atomicAdd(&g_bcnt[b * NBIN + d], (unsigned)__popc(grp));
            base = __shfl_sync(grp, base, leader);
            unsigned slot = base + rank;
            if (slot < BCAP) {
                int a = q * 4 + l;
                g_bucket[((size_t)b * NBIN + d) * BCAP + slot] =
                    ((unsigned long long)__float_as_uint(sv[l]) << 32) | (unsigned)(~a);
            }
        }
    }
}

// ---------------------------------------------------------------------------
// K3: per-frame — pivot, PARALLEL superset gather (binary search on prefix),
// sort (exact top-750 order), NMS, fused gather. Resets counts for replay.
// ---------------------------------------------------------------------------
__global__ __launch_bounds__(1024) void k_select(const float* __restrict__ raw,
                                                 const float* __restrict__ vid,
                                                 const float* __restrict__ reg,
                                                 float* __restrict__ out) {
    const int b = blockIdx.x;
    const int tid = threadIdx.x;
    const int T = 1024;

    __shared__ unsigned long long keys[1024];
    __shared__ unsigned cnts[NBIN];
    __shared__ unsigned prefs[NBIN];
    __shared__ float bx1[PRE], by1[PRE], bx2[PRE], by2[PRE], barea[PRE];
    __shared__ int bcls[PRE];
    __shared__ int keep[PRE];
    __shared__ unsigned pairs[1024];
    __shared__ int sh_final[POST];
    __shared__ unsigned hist[256];
    __shared__ unsigned wsum[32];
    __shared__ unsigned long long sh_prefix;
    __shared__ unsigned sh_k;
    __shared__ int sh_pos, sh_maxbits, sh_np, sh_kept, sh_fallback;
    __shared__ int sh_p, sh_total, sh_over;

    const float* ms = g_maxs + (size_t)b * An;
    const int* cl = g_cls + (size_t)b * An;
    unsigned* BC = g_bcnt + (size_t)b * NBIN;

    // ---- load counts (2 bins/thread), block scan, pivot bin ----
    uint2 c2 = ((const uint2*)BC)[tid];
    cnts[2 * tid] = c2.x;
    cnts[2 * tid + 1] = c2.y;
    unsigned s = c2.x + c2.y;

    unsigned lane = tid & 31, wid = tid >> 5;
    unsigned v = s;
#pragma unroll
    for (int o = 1; o < 32; o <<= 1) {
        unsigned n = __shfl_up_sync(0xFFFFFFFFu, v, o);
        if (lane >= o) v += n;
    }
    if (lane == 31) wsum[wid] = v;
    __syncthreads();
    if (wid == 0) {
        unsigned w = wsum[lane];
#pragma unroll
        for (int o = 1; o < 32; o <<= 1) {
            unsigned n = __shfl_up_sync(0xFFFFFFFFu, w, o);
            if (lane >= o) w += n;
        }
        wsum[lane] = w;
    }
    if (tid == 0) sh_over = 0;
    __syncthreads();
    unsigned incl = v + (wid ? wsum[wid - 1] : 0u);
    unsigned excl = incl - s;
    prefs[2 * tid] = excl;
    prefs[2 * tid + 1] = excl + c2.x;

    if (excl < PRE && incl >= PRE) {
        int p = (excl + c2.x >= PRE) ? (2 * tid) : (2 * tid + 1);
        sh_p = p;
        sh_total = (int)(prefs[p] + cnts[p]);
    }
    __syncthreads();
    int p = sh_p;
    int total = sh_total;
    if ((int)(2 * tid) <= p && c2.x > BCAP) sh_over = 1;
    if ((int)(2 * tid + 1) <= p && c2.y > BCAP) sh_over = 1;
    __syncthreads();

    if (total <= 1024 && !sh_over) {
        // ---- PARALLEL gather: one key per thread via prefix binary search ----
        if (tid < total) {
            int lo = 0, hi = p;   // largest bin in [0,p] with prefs[bin] <= tid
            while (lo < hi) {
                int mid = (lo + hi + 1) >> 1;
                if (prefs[mid] <= (unsigned)tid) lo = mid; else hi = mid - 1;
            }
            unsigned k = (unsigned)tid - prefs[lo];
            keys[tid] = g_bucket[((size_t)b * NBIN + lo) * BCAP + k];
        } else {
            keys[tid] = 0ULL;
        }
    } else {
        // ---- exact fallback: 8-pass 64-bit radix select over g_maxs ----
        unsigned long long prefix = 0ULL;
        unsigned kk = PRE;
        const int ITER = (An + T - 1) / T;
        for (int pass = 0; pass < 8; ++pass) {
            int shift = 56 - pass * 8;
            unsigned long long hi_mask = (pass == 0) ? 0ULL : (~0ULL << (unsigned)(shift + 8));
            for (int i = tid; i < 256; i += T) hist[i] = 0;
            __syncthreads();
            for (int it = 0; it < ITER; ++it) {
                int a = it * T + tid;
                if (a < An) {
                    unsigned long long key =
                        ((unsigned long long)__float_as_uint(ms[a]) << 32) | (unsigned)(~a);
                    if ((key & hi_mask) == prefix)
                        atomicAdd(&hist[(unsigned)(key >> shift) & 255u], 1u);
                }
            }
            __syncthreads();
            if (tid == 0) {
                unsigned cum = 0; int d = 255;
                for (; d >= 0; --d) {
                    unsigned c = hist[d];
                    if (cum + c >= kk) break;
                    cum += c;
                }
                if (d < 0) d = 0;
                prefix |= ((unsigned long long)d) << shift;
                kk -= cum;
                sh_prefix = prefix; sh_k = kk;
            }
            __syncthreads();
            prefix = sh_prefix; kk = sh_k;
            __syncthreads();
        }
        if (tid == 0) sh_pos = 0;
        __syncthreads();
        for (int a = tid; a < An; a += T) {
            unsigned long long key =
                ((unsigned long long)__float_as_uint(ms[a]) << 32) | (unsigned)(~a);
            if (key >= prefix) {
                int pos = atomicAdd(&sh_pos, 1);
                if (pos < 1024) keys[pos] = key;
            }
        }
        __syncthreads();
        int cpos = sh_pos; if (cpos > 1024) cpos = 1024;
        for (int i = cpos + tid; i < 1024; i += T) keys[i] = 0ULL;
    }

    // reset bucket counts for graph replay (after all reads of BC)
    ((uint2*)BC)[tid] = make_uint2(0, 0);
    __syncthreads();

    // ---- hybrid bitonic sort, descending by true key ----
    {
        unsigned long long vv = keys[tid];
        for (int k2 = 2; k2 <= 1024; k2 <<= 1) {
            bool dirmax = ((tid & k2) == 0);
            for (int j = k2 >> 1; j >= 1; j >>= 1) {
                unsigned long long o;
                if (j >= 32) {
                    keys[tid] = vv;
                    __syncthreads();
                    o = keys[tid ^ j];
                    __syncthreads();
                } else {
                    o = __shfl_xor_sync(0xFFFFFFFFu, vv, j);
                }
                bool lower = ((tid & j) == 0);
                bool takeMax = (lower == dirmax);
                bool gt = (vv > o);
                vv = (takeMax == gt) ? vv : o;
            }
        }
        keys[tid] = vv;
        __syncthreads();
    }

    // ---- boxes/classes for sorted top-750; max coordinate ----
    if (tid == 0) { sh_maxbits = 0; sh_fallback = 0; }
    __syncthreads();
    if (tid < PRE) {
        int i = tid;
        int a = (int)(~(unsigned)(keys[i] & 0xFFFFFFFFULL));
        const float* rb = raw + (size_t)b * 84 * An;
        float x1 = rb[0 * (size_t)An + a];
        float y1 = rb[1 * (size_t)An + a];
        float x2 = rb[2 * (size_t)An + a];
        float y2 = rb[3 * (size_t)An + a];
        bx1[i] = x1; by1[i] = y1; bx2[i] = x2; by2[i] = y2;
        bcls[i] = cl[a];
        float m = fmaxf(fmaxf(x1, y1), fmaxf(x2, y2));
        atomicMax(&sh_maxbits, __float_as_int(m));
    }
    __syncthreads();

    float off_scale = __int_as_float(sh_maxbits) + 1.0f;
    if (tid < PRE) {
        int i = tid;
        float off = (float)bcls[i] * off_scale;
        float x1 = bx1[i] + off, y1 = by1[i] + off;
        float x2 = bx2[i] + off, y2 = by2[i] + off;
        bx1[i] = x1; by1[i] = y1; bx2[i] = x2; by2[i] = y2;
        barea[i] = (x2 - x1) * (y2 - y1);
    }
    __syncthreads();

    // ---- NMS: windowed conflict pairs + serial resolve ----
    {
        int W = 64;
        for (;;) {
            if (tid == 0) sh_np = 0;
            if (tid < PRE) keep[tid] = 1;
            __syncthreads();

            for (int pp = tid; pp < W * PRE; pp += T) {
                int i = pp / PRE;
                int j = pp - i * PRE;
                if (j > i && bcls[i] == bcls[j]) {
                    float iw = fmaxf(fminf(bx2[i], bx2[j]) - fmaxf(bx1[i], bx1[j]), 0.0f);
                    float ih = fmaxf(fminf(by2[i], by2[j]) - fmaxf(by1[i], by1[j]), 0.0f);
                    float inter = iw * ih;
                    float iou = __fdiv_rn(inter, barea[i] + barea[j] - inter);
                    if (iou > 0.4f) {
                        int k = atomicAdd(&sh_np, 1);
                        if (k < 1024) pairs[k] = ((unsigned)i << 10) | (unsigned)j;
                    }
                }
            }
            __syncthreads();
            int np = sh_np;
            if (np > 1024) { if (tid == 0) sh_fallback = 1; __syncthreads(); break; }

            if (tid == 0) {
                for (int a2 = 1; a2 < np; ++a2) {
                    unsigned pv = pairs[a2];
                    int b2 = a2 - 1;
                    while (b2 >= 0 && pairs[b2] > pv) { pairs[b2 + 1] = pairs[b2]; --b2; }
                    pairs[b2 + 1] = pv;
                }
                for (int p2 = 0; p2 < np; ++p2) {
                    unsigned pv = pairs[p2];
                    int i = (int)(pv >> 10), j = (int)(pv & 1023u);
                    if (keep[i]) keep[j] = 0;
                }
                int kept = 0;
                for (int i = 0; i < W && kept < POST; ++i) kept += keep[i];
                sh_kept = kept;
            }
            __syncthreads();
            if (sh_kept >= POST || W >= PRE) break;
            W = (W * 4 < PRE) ? W * 4 : PRE;
            __syncthreads();
        }
    }

    if (sh_fallback) {  // pathological conflict counts only
        if (tid < PRE) keep[tid] = 1;
        __syncthreads();
        int i = 0, kept = 0;
        while (i < PRE && kept < POST) {
            while (i < PRE && !keep[i]) ++i;
            if (i >= PRE) break;
            float X1 = bx1[i], Y1 = by1[i], X2 = bx2[i], Y2 = by2[i], AR = barea[i];
            int CI = bcls[i];
            for (int j = i + 1 + tid; j < PRE; j += T) {
                if (keep[j] && bcls[j] == CI) {
                    float iw = fmaxf(fminf(X2, bx2[j]) - fmaxf(X1, bx1[j]), 0.0f);
                    float ih = fmaxf(fminf(Y2, by2[j]) - fmaxf(Y1, by1[j]), 0.0f);
                    float inter = iw * ih;
                    float iou = __fdiv_rn(inter, AR + barea[j] - inter);
                    if (iou > 0.4f) keep[j] = 0;
                }
            }
            ++kept; ++i;
            __syncthreads();
        }
    }

    // ---- stable-partition: first 30 kept, then unkept fill ----
    if (tid == 0) {
        int c3 = 0;
        for (int i = 0; i < PRE && c3 < POST; ++i)
            if (keep[i]) sh_final[c3++] = i;
        for (int i = 0; i < PRE && c3 < POST; ++i)
            if (!keep[i]) sh_final[c3++] = i;
    }
    __syncthreads();

    // ---- fused gather ----
    for (int w2 = tid; w2 < POST * 128; w2 += T) {
        int c = w2 >> 7;
        int f = w2 & 127;
        int i = sh_final[c];
        int a = (int)(~(unsigned)(keys[i] & 0xFFFFFFFFULL));
        size_t r = (size_t)b * POST + c;
        size_t row = ((size_t)b * An + a) * CH;
        if (f < 64)
            ((float4*)(out + OUT_CLS_OFF))[r * 64 + f] = __ldg((const float4*)(vid + row) + f);
        else
            ((float4*)(out + OUT_REG_OFF))[r * 64 + (f - 64)] = __ldg((const float4*)(reg + row) + (f - 64));
    }
    if (tid < POST * 4) {
        int c = tid >> 2, d = tid & 3;
        int i = sh_final[c];
        int a = (int)(~(unsigned)(keys[i] & 0xFFFFFFFFULL));
        out[OUT_BOX_OFF + (b * POST + c) * 4 + d] = raw[(size_t)b * 84 * An + (size_t)d * An + a];
    }
    if (tid >= 128 && tid < 128 + POST) {
        int c = tid - 128;
        int i = sh_final[c];
        out[OUT_SC_OFF + b * POST + c] = __uint_as_float((unsigned)(keys[i] >> 32));
    }
}

// ---------------------------------------------------------------------------
extern "C" void kernel_launch(void* const* d_in, const int* in_sizes, int n_in,
                              void* d_out, int out_size) {
    const float* raw = (const float*)d_in[0];
    const float* vid = (const float*)d_in[1];
    const float* reg = (const float*)d_in[2];
    float* out = (float*)d_out;

    int threads1 = 256;
    int blocks1 = (Bn * HAn + threads1 - 1) / threads1;   // 1050
    dim3 g2(FBLK, Bn);
    k_maxscore<<<blocks1, threads1>>>(raw);
    k_scatter<<<g2, 256>>>();
    k_select<<<Bn, 1024>>>(raw, vid, reg, out);
}